// round 7
// baseline (speedup 1.0000x reference)
#include <cuda_runtime.h>

// Problem constants
#define NB   2048      // B*T tokens
#define DD   1024      // model dim
#define EE   16        // experts
#define FF   512       // expert hidden
#define F2   1024      // 2*FF
#define FSH  2048      // shared expert hidden
#define CAP  2048      // per-expert token capacity (worst case)
#define OUT_ELEMS (NB*DD)

// ---------------- scratch (device globals; ~80 MiB total) ------------------
__device__ float g_probs[NB * EE];                // 128 KiB
__device__ float g_sgate[NB];                     // 8 KiB
__device__ int   g_cnt[EE];
__device__ int   g_tok[EE * CAP];                 // 128 KiB
__device__ float g_wgt[EE * CAP];                 // 128 KiB
__device__ float g_H[(size_t)EE * CAP * FF];      // 64 MiB : silu(g)*u per slot
__device__ float g_SH[(size_t)NB * FSH];          // 16 MiB : shared silu(g)*u

__device__ __forceinline__ float silu_f(float v) { return v / (1.f + __expf(-v)); }

// ------------------------- small kernels -----------------------------------
__global__ void init_kernel() {
    if (threadIdx.x < EE) g_cnt[threadIdx.x] = 0;
}

// One block per token: router logits, softmax, top-2, scatter, shared gate.
// No runtime-indexed local arrays; only __expf (no libdevice slow paths).
__global__ void __launch_bounds__(128) router_kernel(
    const float* __restrict__ x, const float* __restrict__ rw,
    const float* __restrict__ sgw)
{
    const int t = blockIdx.x;
    __shared__ float xs[DD];
    __shared__ float red[128];
    __shared__ float logits[EE];
    const float* xp = x + (size_t)t * DD;
    for (int i = threadIdx.x; i < DD / 4; i += 128)
        ((float4*)xs)[i] = ((const float4*)xp)[i];
    __syncthreads();

    // 8 threads per expert
    const int e = threadIdx.x >> 3;
    const int j = threadIdx.x & 7;
    float s = 0.f;
    for (int d = j; d < DD; d += 8) s += xs[d] * rw[d * EE + e];
    s += __shfl_down_sync(0xffffffffu, s, 4);
    s += __shfl_down_sync(0xffffffffu, s, 2);
    s += __shfl_down_sync(0xffffffffu, s, 1);
    if (j == 0) logits[e] = s;

    // shared gate dot
    float g = 0.f;
    for (int d = threadIdx.x; d < DD; d += 128) g += xs[d] * sgw[d];
    red[threadIdx.x] = g;
    __syncthreads();
    for (int off = 64; off > 0; off >>= 1) {
        if (threadIdx.x < off) red[threadIdx.x] += red[threadIdx.x + off];
        __syncthreads();
    }

    if (threadIdx.x == 0) {
        float m = logits[0];
        #pragma unroll
        for (int k = 1; k < EE; k++) m = fmaxf(m, logits[k]);
        float sum = 0.f;
        #pragma unroll
        for (int k = 0; k < EE; k++) {
            float ek = __expf(logits[k] - m);
            logits[k] = ek;
            sum += ek;
        }
        const float inv = 1.f / sum;
        // top-2 via scalar register tracking; ">" keeps lowest index on ties.
        float m1 = -1.f, m2 = -1.f;
        int   i1 = 0,    i2 = 0;
        #pragma unroll
        for (int k = 0; k < EE; k++) {
            float pk = logits[k] * inv;
            g_probs[t * EE + k] = pk;
            if (pk > m1)      { m2 = m1; i2 = i1; m1 = pk; i1 = k; }
            else if (pk > m2) { m2 = pk; i2 = k; }
        }
        const float denom = fmaxf(m1 + m2, 1e-9f);
        int s0 = atomicAdd(&g_cnt[i1], 1);
        g_tok[i1 * CAP + s0] = t; g_wgt[i1 * CAP + s0] = m1 / denom;
        int s1 = atomicAdd(&g_cnt[i2], 1);
        g_tok[i2 * CAP + s1] = t; g_wgt[i2 * CAP + s1] = m2 / denom;
        g_sgate[t] = 1.f / (1.f + __expf(-red[0]));
    }
}

// Deterministic aux-loss reduction (16 warps, one per expert).
__global__ void __launch_bounds__(512) aux_kernel(float* __restrict__ out, int out_size)
{
    const int w = threadIdx.x >> 5;
    const int l = threadIdx.x & 31;
    float s = 0.f;
    for (int t = l; t < NB; t += 32) s += g_probs[t * EE + w];
    #pragma unroll
    for (int off = 16; off > 0; off >>= 1) s += __shfl_down_sync(0xffffffffu, s, off);
    __shared__ float ls[EE];
    if (l == 0) ls[w] = s;
    __syncthreads();
    if (threadIdx.x == 0) {
        float a = 0.f;
        #pragma unroll
        for (int e = 0; e < EE; e++) {
            float load = ls[e] * (1.f / (float)NB);
            float d = load - 1.f / (float)EE;
            a += d * d;
        }
        if (out_size > OUT_ELEMS) out[OUT_ELEMS] = 0.001f * a;
    }
}

// ---------------- fused MoE gate+up GEMM (NT, dual accumulator) ------------
// Block: 128 gathered tokens x 64 f-values. K = DD.
// h[slot, f] = silu(x@Wg_f) * (x@Wu_f), Wg row f, Wu row FF+f of gate_up_proj.
__global__ void __launch_bounds__(256) moe_gateup_kernel(
    const float* __restrict__ x, const float* __restrict__ gup)
{
    const int e = blockIdx.z;
    const int cnt_e = g_cnt[e];
    const int bm = blockIdx.y;
    if (bm * 128 >= cnt_e) return;
    const int bn = blockIdx.x;          // f-tile (64 wide)
    const int seg = e * CAP;

    __shared__ float As[16][128];
    __shared__ float Bg[16][64];
    __shared__ float Bu[16][64];
    const int tid = threadIdx.x;
    const int tx = tid & 15;            // n: 4 cols each
    const int ty = tid >> 4;            // m: 8 rows each

    // A gather: one row per thread
    const int am = tid >> 1;            // 0..127
    const int ak = (tid & 1) << 3;      // 0 or 8
    const int r = bm * 128 + am;
    const int gi = (r < cnt_e) ? g_tok[seg + r] : 0;
    const float* pA = x + (size_t)gi * DD;

    // B: row per 4 threads
    const int bnr = tid >> 2;           // 0..63
    const int bk  = (tid & 3) << 2;     // 0,4,8,12
    const float* pBg = gup + ((size_t)e * F2 + (size_t)(bn * 64 + bnr)) * DD;
    const float* pBu = pBg + (size_t)FF * DD;

    float4 ra0 = *(const float4*)(pA + ak);
    float4 ra1 = *(const float4*)(pA + ak + 4);
    float4 rg  = *(const float4*)(pBg + bk);
    float4 ru  = *(const float4*)(pBu + bk);

    float accg[8][4], accu[8][4];
    #pragma unroll
    for (int i = 0; i < 8; i++)
        #pragma unroll
        for (int jj = 0; jj < 4; jj++) { accg[i][jj] = 0.f; accu[i][jj] = 0.f; }

    for (int k0 = 0; k0 < DD; k0 += 16) {
        As[ak + 0][am] = ra0.x; As[ak + 1][am] = ra0.y;
        As[ak + 2][am] = ra0.z; As[ak + 3][am] = ra0.w;
        As[ak + 4][am] = ra1.x; As[ak + 5][am] = ra1.y;
        As[ak + 6][am] = ra1.z; As[ak + 7][am] = ra1.w;
        Bg[bk + 0][bnr] = rg.x; Bg[bk + 1][bnr] = rg.y;
        Bg[bk + 2][bnr] = rg.z; Bg[bk + 3][bnr] = rg.w;
        Bu[bk + 0][bnr] = ru.x; Bu[bk + 1][bnr] = ru.y;
        Bu[bk + 2][bnr] = ru.z; Bu[bk + 3][bnr] = ru.w;
        __syncthreads();
        const int k1 = k0 + 16;
        if (k1 < DD) {
            ra0 = *(const float4*)(pA + k1 + ak);
            ra1 = *(const float4*)(pA + k1 + ak + 4);
            rg  = *(const float4*)(pBg + k1 + bk);
            ru  = *(const float4*)(pBu + k1 + bk);
        }
        #pragma unroll
        for (int kk = 0; kk < 16; kk++) {
            float a[8], bg[4], bu[4];
            *(float4*)&a[0] = *(const float4*)&As[kk][ty * 8];
            *(float4*)&a[4] = *(const float4*)&As[kk][ty * 8 + 4];
            *(float4*)&bg[0] = *(const float4*)&Bg[kk][tx * 4];
            *(float4*)&bu[0] = *(const float4*)&Bu[kk][tx * 4];
            #pragma unroll
            for (int i = 0; i < 8; i++)
                #pragma unroll
                for (int jj = 0; jj < 4; jj++) {
                    accg[i][jj] = fmaf(a[i], bg[jj], accg[i][jj]);
                    accu[i][jj] = fmaf(a[i], bu[jj], accu[i][jj]);
                }
        }
        __syncthreads();
    }
    #pragma unroll
    for (int i = 0; i < 8; i++) {
        const int rloc = bm * 128 + ty * 8 + i;
        if (rloc < cnt_e) {
            float* hp = g_H + (size_t)(seg + rloc) * FF + bn * 64 + tx * 4;
            float4 hv;
            hv.x = silu_f(accg[i][0]) * accu[i][0];
            hv.y = silu_f(accg[i][1]) * accu[i][1];
            hv.z = silu_f(accg[i][2]) * accu[i][2];
            hv.w = silu_f(accg[i][3]) * accu[i][3];
            *(float4*)hp = hv;
        }
    }
}

// ---------------- fused shared-expert gate+up GEMM (NN, dual acc) ----------
// Block: 128 tokens x 64 hidden. K = DD. B matrices shg/shu are [DD, FSH].
__global__ void __launch_bounds__(256) shared_gateup_kernel(
    const float* __restrict__ x, const float* __restrict__ shg,
    const float* __restrict__ shu)
{
    const int bm = blockIdx.y;
    const int bn = blockIdx.x;          // 64-wide hidden tile

    __shared__ float As[16][128];
    __shared__ float Bg[16][64];
    __shared__ float Bu[16][64];
    const int tid = threadIdx.x;
    const int tx = tid & 15;
    const int ty = tid >> 4;

    const int am = tid >> 1;
    const int ak = (tid & 1) << 3;
    const float* pA = x + (size_t)(bm * 128 + am) * DD;

    const int bkr  = tid >> 4;          // 0..15 (k row)
    const int bc4  = (tid & 15) << 2;   // 0..60 (n col, x4)
    const float* pBg = shg + (size_t)bkr * FSH + bn * 64 + bc4;
    const float* pBu = shu + (size_t)bkr * FSH + bn * 64 + bc4;

    float4 ra0 = *(const float4*)(pA + ak);
    float4 ra1 = *(const float4*)(pA + ak + 4);
    float4 rg  = *(const float4*)(pBg);
    float4 ru  = *(const float4*)(pBu);

    float accg[8][4], accu[8][4];
    #pragma unroll
    for (int i = 0; i < 8; i++)
        #pragma unroll
        for (int jj = 0; jj < 4; jj++) { accg[i][jj] = 0.f; accu[i][jj] = 0.f; }

    for (int k0 = 0; k0 < DD; k0 += 16) {
        As[ak + 0][am] = ra0.x; As[ak + 1][am] = ra0.y;
        As[ak + 2][am] = ra0.z; As[ak + 3][am] = ra0.w;
        As[ak + 4][am] = ra1.x; As[ak + 5][am] = ra1.y;
        As[ak + 6][am] = ra1.z; As[ak + 7][am] = ra1.w;
        *(float4*)&Bg[bkr][bc4] = rg;
        *(float4*)&Bu[bkr][bc4] = ru;
        __syncthreads();
        const int k1 = k0 + 16;
        if (k1 < DD) {
            ra0 = *(const float4*)(pA + k1 + ak);
            ra1 = *(const float4*)(pA + k1 + ak + 4);
            rg  = *(const float4*)(pBg + (size_t)k1 * FSH);
            ru  = *(const float4*)(pBu + (size_t)k1 * FSH);
        }
        #pragma unroll
        for (int kk = 0; kk < 16; kk++) {
            float a[8], bg[4], bu[4];
            *(float4*)&a[0] = *(const float4*)&As[kk][ty * 8];
            *(float4*)&a[4] = *(const float4*)&As[kk][ty * 8 + 4];
            *(float4*)&bg[0] = *(const float4*)&Bg[kk][tx * 4];
            *(float4*)&bu[0] = *(const float4*)&Bu[kk][tx * 4];
            #pragma unroll
            for (int i = 0; i < 8; i++)
                #pragma unroll
                for (int jj = 0; jj < 4; jj++) {
                    accg[i][jj] = fmaf(a[i], bg[jj], accg[i][jj]);
                    accu[i][jj] = fmaf(a[i], bu[jj], accu[i][jj]);
                }
        }
        __syncthreads();
    }
    #pragma unroll
    for (int i = 0; i < 8; i++) {
        float* sp = g_SH + (size_t)(bm * 128 + ty * 8 + i) * FSH + bn * 64 + tx * 4;
        float4 sv;
        sv.x = silu_f(accg[i][0]) * accu[i][0];
        sv.y = silu_f(accg[i][1]) * accu[i][1];
        sv.z = silu_f(accg[i][2]) * accu[i][2];
        sv.w = silu_f(accg[i][3]) * accu[i][3];
        *(float4*)sp = sv;
    }
}

// ---------------- shared-expert down GEMM (NN) -> writes out ---------------
// out[t, d] = g_sgate[t] * (g_SH[t, :] @ shd[:, d]).  K = FSH.
__global__ void __launch_bounds__(256) shared_down_kernel(
    const float* __restrict__ shd, float* __restrict__ out)
{
    __shared__ float As[16][128];
    __shared__ float Bs[16][128];
    const int tid = threadIdx.x;
    const int bm = blockIdx.y, bn = blockIdx.x;
    const int tx = tid & 15, ty = tid >> 4;

    const int am = tid >> 1;
    const int ak = (tid & 1) << 3;
    const float* pA = g_SH + (size_t)(bm * 128 + am) * FSH;

    const int bkr = tid >> 5;            // 0..7, rows bkr & bkr+8
    const int bn4 = (tid & 31) << 2;     // 0..124
    const float* pB = shd + bn * 128 + bn4;

    float4 ra0 = *(const float4*)(pA + ak);
    float4 ra1 = *(const float4*)(pA + ak + 4);
    float4 rb0 = *(const float4*)(pB + (size_t)bkr * DD);
    float4 rb1 = *(const float4*)(pB + (size_t)(bkr + 8) * DD);

    float acc[8][8];
    #pragma unroll
    for (int i = 0; i < 8; i++)
        #pragma unroll
        for (int j = 0; j < 8; j++) acc[i][j] = 0.f;

    for (int k0 = 0; k0 < FSH; k0 += 16) {
        As[ak + 0][am] = ra0.x; As[ak + 1][am] = ra0.y;
        As[ak + 2][am] = ra0.z; As[ak + 3][am] = ra0.w;
        As[ak + 4][am] = ra1.x; As[ak + 5][am] = ra1.y;
        As[ak + 6][am] = ra1.z; As[ak + 7][am] = ra1.w;
        *(float4*)&Bs[bkr][bn4]     = rb0;
        *(float4*)&Bs[bkr + 8][bn4] = rb1;
        __syncthreads();
        const int k1 = k0 + 16;
        if (k1 < FSH) {
            ra0 = *(const float4*)(pA + k1 + ak);
            ra1 = *(const float4*)(pA + k1 + ak + 4);
            rb0 = *(const float4*)(pB + (size_t)(k1 + bkr) * DD);
            rb1 = *(const float4*)(pB + (size_t)(k1 + bkr + 8) * DD);
        }
        #pragma unroll
        for (int kk = 0; kk < 16; kk++) {
            float a[8], b[8];
            *(float4*)&a[0] = *(const float4*)&As[kk][ty * 8];
            *(float4*)&a[4] = *(const float4*)&As[kk][ty * 8 + 4];
            *(float4*)&b[0] = *(const float4*)&Bs[kk][tx * 8];
            *(float4*)&b[4] = *(const float4*)&Bs[kk][tx * 8 + 4];
            #pragma unroll
            for (int i = 0; i < 8; i++)
                #pragma unroll
                for (int j = 0; j < 8; j++)
                    acc[i][j] = fmaf(a[i], b[j], acc[i][j]);
        }
        __syncthreads();
    }
    #pragma unroll
    for (int i = 0; i < 8; i++) {
        const int row = bm * 128 + ty * 8 + i;
        const float sg = g_sgate[row];
        float* op = out + (size_t)row * DD + bn * 128 + tx * 8;
        *(float4*)(op)     = make_float4(sg * acc[i][0], sg * acc[i][1], sg * acc[i][2], sg * acc[i][3]);
        *(float4*)(op + 4) = make_float4(sg * acc[i][4], sg * acc[i][5], sg * acc[i][6], sg * acc[i][7]);
    }
}

// ---------------- MoE down GEMM (NT) -> atomicAdd into out -----------------
// out[tok, d] += wgt * (g_H[slot, :] @ dwn[e, d, :]).  K = FF = 512.
__global__ void __launch_bounds__(256) moe_down_kernel(
    const float* __restrict__ dwn, float* __restrict__ out)
{
    const int e = blockIdx.z;
    const int cnt_e = g_cnt[e];
    const int bm = blockIdx.y;
    if (bm * 128 >= cnt_e) return;
    const int bn = blockIdx.x;
    const int seg = e * CAP;

    __shared__ float As[16][128];
    __shared__ float Bs[16][128];
    const int tid = threadIdx.x;
    const int tx = tid & 15, ty = tid >> 4;

    const int am = tid >> 1;
    const int ak = (tid & 1) << 3;
    const float* pA = g_H + (size_t)(seg + bm * 128 + am) * FF;

    const int bnr = tid >> 1;            // 0..127: one B row (d) per thread pair? no:
    // 128 rows x 16 k = 2048 floats; 256 threads x 8 floats (2 float4)
    const float* pB = dwn + ((size_t)e * DD + (size_t)(bn * 128 + bnr)) * FF;

    float4 ra0 = *(const float4*)(pA + ak);
    float4 ra1 = *(const float4*)(pA + ak + 4);
    float4 rb0 = *(const float4*)(pB + ak);
    float4 rb1 = *(const float4*)(pB + ak + 4);

    float acc[8][8];
    #pragma unroll
    for (int i = 0; i < 8; i++)
        #pragma unroll
        for (int j = 0; j < 8; j++) acc[i][j] = 0.f;

    for (int k0 = 0; k0 < FF; k0 += 16) {
        As[ak + 0][am] = ra0.x; As[ak + 1][am] = ra0.y;
        As[ak + 2][am] = ra0.z; As[ak + 3][am] = ra0.w;
        As[ak + 4][am] = ra1.x; As[ak + 5][am] = ra1.y;
        As[ak + 6][am] = ra1.z; As[ak + 7][am] = ra1.w;
        Bs[ak + 0][bnr] = rb0.x; Bs[ak + 1][bnr] = rb0.y;
        Bs[ak + 2][bnr] = rb0.z; Bs[ak + 3][bnr] = rb0.w;
        Bs[ak + 4][bnr] = rb1.x; Bs[ak + 5][bnr] = rb1.y;
        Bs[ak + 6][bnr] = rb1.z; Bs[ak + 7][bnr] = rb1.w;
        __syncthreads();
        const int k1 = k0 + 16;
        if (k1 < FF) {
            ra0 = *(const float4*)(pA + k1 + ak);
            ra1 = *(const float4*)(pA + k1 + ak + 4);
            rb0 = *(const float4*)(pB + k1 + ak);
            rb1 = *(const float4*)(pB + k1 + ak + 4);
        }
        #pragma unroll
        for (int kk = 0; kk < 16; kk++) {
            float a[8], b[8];
            *(float4*)&a[0] = *(const float4*)&As[kk][ty * 8];
            *(float4*)&a[4] = *(const float4*)&As[kk][ty * 8 + 4];
            *(float4*)&b[0] = *(const float4*)&Bs[kk][tx * 8];
            *(float4*)&b[4] = *(const float4*)&Bs[kk][tx * 8 + 4];
            #pragma unroll
            for (int i = 0; i < 8; i++)
                #pragma unroll
                for (int j = 0; j < 8; j++)
                    acc[i][j] = fmaf(a[i], b[j], acc[i][j]);
        }
        __syncthreads();
    }
    #pragma unroll
    for (int i = 0; i < 8; i++) {
        const int rloc = bm * 128 + ty * 8 + i;
        if (rloc < cnt_e) {
            const int   tok = g_tok[seg + rloc];
            const float w   = g_wgt[seg + rloc];
            float* op = out + (size_t)tok * DD + bn * 128 + tx * 8;
            #pragma unroll
            for (int j = 0; j < 8; j++)
                atomicAdd(op + j, w * acc[i][j]);
        }
    }
}

// ------------------------- launch ------------------------------------------
extern "C" void kernel_launch(void* const* d_in, const int* in_sizes, int n_in,
                              void* d_out, int out_size)
{
    const float* x   = (const float*)d_in[0];   // [B,T,D]
    const float* gup = (const float*)d_in[1];   // [E,2F,D]
    const float* dwn = (const float*)d_in[2];   // [E,D,F]
    const float* rw  = (const float*)d_in[3];   // [D,E]
    const float* shg = (const float*)d_in[4];   // [D,FS]
    const float* shu = (const float*)d_in[5];   // [D,FS]
    const float* shd = (const float*)d_in[6];   // [FS,D]
    const float* sgw = (const float*)d_in[7];   // [D,1]
    float* out = (float*)d_out;

    // Router + scatter + aux
    init_kernel<<<1, 32>>>();
    router_kernel<<<NB, 128>>>(x, rw, sgw);
    aux_kernel<<<1, 512>>>(out, out_size);

    // Shared expert: fused gate/up (silu epilogue), then down -> out
    {
        dim3 grid(FSH / 64, NB / 128);          // (32,16)
        shared_gateup_kernel<<<grid, 256>>>(x, shg, shu);
    }
    {
        dim3 grid(DD / 128, NB / 128);          // (8,16)
        shared_down_kernel<<<grid, 256>>>(shd, out);
    }

    // MoE expert path: fused gate/up (silu epilogue), down accumulates to out
    {
        dim3 grid(FF / 64, CAP / 128, EE);      // (8,16,16)
        moe_gateup_kernel<<<grid, 256>>>(x, gup);
    }
    {
        dim3 grid(DD / 128, CAP / 128, EE);     // (8,16,16)
        moe_down_kernel<<<grid, 256>>>(dwn, out);
    }
}

// round 15
// speedup vs baseline: 1.0362x; 1.0362x over previous
#include <cuda_runtime.h>
#include <math.h>

// Problem constants
#define NB   2048      // B*T tokens
#define DD   1024      // model dim
#define EE   16        // experts
#define FF   512       // expert hidden
#define F2   1024      // 2*FF
#define FSH  2048      // shared expert hidden
#define CAP  2048      // per-expert token capacity (worst case)
#define OUT_ELEMS (NB*DD)

// ---------------- scratch (device globals; ~80 MiB total) ------------------
__device__ float g_probs[NB * EE];
__device__ float g_sgate[NB];
__device__ int   g_cnt[EE];
__device__ int   g_tok[EE * CAP];
__device__ float g_wgt[EE * CAP];
__device__ float g_H[(size_t)EE * CAP * FF];      // 64 MiB : silu(g)*u per slot
__device__ float g_SH[(size_t)NB * FSH];          // 16 MiB : shared silu(g)*u

__device__ __forceinline__ float silu_f(float v) { return v / (1.f + __expf(-v)); }

// ---- packed f32x2 helpers (register-only asm; Blackwell FFMA2 path) -------
typedef unsigned long long ull;
__device__ __forceinline__ ull pack2(float lo, float hi) {
    ull r;
    asm("mov.b64 %0, {%1, %2};" : "=l"(r) : "f"(lo), "f"(hi));
    return r;
}
__device__ __forceinline__ void fma2(ull& d, ull a, ull b) {
    asm("fma.rn.f32x2 %0, %1, %2, %0;" : "+l"(d) : "l"(a), "l"(b));
}
__device__ __forceinline__ void unpack2(ull v, float& lo, float& hi) {
    asm("mov.b64 {%0, %1}, %2;" : "=f"(lo), "=f"(hi) : "l"(v));
}

// ------------------------- small kernels -----------------------------------
__global__ void init_kernel() {
    if (threadIdx.x < EE) g_cnt[threadIdx.x] = 0;
}

// One block per token: router logits, softmax, top-2, scatter, shared gate.
__global__ void __launch_bounds__(128) router_kernel(
    const float* __restrict__ x, const float* __restrict__ rw,
    const float* __restrict__ sgw)
{
    const int t = blockIdx.x;
    __shared__ float xs[DD];
    __shared__ float red[128];
    __shared__ float logits[EE];
    const float* xp = x + (size_t)t * DD;
    for (int i = threadIdx.x; i < DD / 4; i += 128)
        ((float4*)xs)[i] = ((const float4*)xp)[i];
    __syncthreads();

    const int e = threadIdx.x >> 3;
    const int j = threadIdx.x & 7;
    float s = 0.f;
    for (int d = j; d < DD; d += 8) s += xs[d] * rw[d * EE + e];
    s += __shfl_down_sync(0xffffffffu, s, 4);
    s += __shfl_down_sync(0xffffffffu, s, 2);
    s += __shfl_down_sync(0xffffffffu, s, 1);
    if (j == 0) logits[e] = s;

    float g = 0.f;
    for (int d = threadIdx.x; d < DD; d += 128) g += xs[d] * sgw[d];
    red[threadIdx.x] = g;
    __syncthreads();
    for (int off = 64; off > 0; off >>= 1) {
        if (threadIdx.x < off) red[threadIdx.x] += red[threadIdx.x + off];
        __syncthreads();
    }

    if (threadIdx.x == 0) {
        float m = logits[0];
        #pragma unroll
        for (int k = 1; k < EE; k++) m = fmaxf(m, logits[k]);
        float sum = 0.f;
        #pragma unroll
        for (int k = 0; k < EE; k++) {
            float ek = __expf(logits[k] - m);
            logits[k] = ek;
            sum += ek;
        }
        const float inv = 1.f / sum;
        float m1 = -1.f, m2 = -1.f;
        int   i1 = 0,    i2 = 0;
        #pragma unroll
        for (int k = 0; k < EE; k++) {
            float pk = logits[k] * inv;
            g_probs[t * EE + k] = pk;
            if (pk > m1)      { m2 = m1; i2 = i1; m1 = pk; i1 = k; }
            else if (pk > m2) { m2 = pk; i2 = k; }
        }
        const float denom = fmaxf(m1 + m2, 1e-9f);
        int s0 = atomicAdd(&g_cnt[i1], 1);
        g_tok[i1 * CAP + s0] = t; g_wgt[i1 * CAP + s0] = m1 / denom;
        int s1 = atomicAdd(&g_cnt[i2], 1);
        g_tok[i2 * CAP + s1] = t; g_wgt[i2 * CAP + s1] = m2 / denom;
        g_sgate[t] = 1.f / (1.f + __expf(-red[0]));
    }
}

__global__ void __launch_bounds__(512) aux_kernel(float* __restrict__ out, int out_size)
{
    const int w = threadIdx.x >> 5;
    const int l = threadIdx.x & 31;
    float s = 0.f;
    for (int t = l; t < NB; t += 32) s += g_probs[t * EE + w];
    #pragma unroll
    for (int off = 16; off > 0; off >>= 1) s += __shfl_down_sync(0xffffffffu, s, off);
    __shared__ float ls[EE];
    if (l == 0) ls[w] = s;
    __syncthreads();
    if (threadIdx.x == 0) {
        float a = 0.f;
        #pragma unroll
        for (int e = 0; e < EE; e++) {
            float load = ls[e] * (1.f / (float)NB);
            float d = load - 1.f / (float)EE;
            a += d * d;
        }
        if (out_size > OUT_ELEMS) out[OUT_ELEMS] = 0.001f * a;
    }
}

// ---------------- fused MoE gate+up GEMM (NT, dual accumulator) ------------
// Block: 128 gathered tokens x 64 f-values. K = DD.
__global__ void __launch_bounds__(256) moe_gateup_kernel(
    const float* __restrict__ x, const float* __restrict__ gup)
{
    const int e = blockIdx.z;
    const int cnt_e = g_cnt[e];
    const int bm = blockIdx.y;
    if (bm * 128 >= cnt_e) return;
    const int bn = blockIdx.x;          // f-tile (64 wide)
    const int seg = e * CAP;

    __shared__ float As[16][128];
    __shared__ float Bg[16][64];
    __shared__ float Bu[16][64];
    const int tid = threadIdx.x;
    const int tx = tid & 15;            // n: 4 cols each
    const int ty = tid >> 4;            // m: 8 rows each

    const int am = tid >> 1;            // 0..127
    const int ak = (tid & 1) << 3;      // 0 or 8
    const int r = bm * 128 + am;
    const int gi = (r < cnt_e) ? g_tok[seg + r] : 0;
    const float* pA = x + (size_t)gi * DD;

    const int bnr = tid >> 2;           // 0..63
    const int bk  = (tid & 3) << 2;     // 0,4,8,12
    const float* pBg = gup + ((size_t)e * F2 + (size_t)(bn * 64 + bnr)) * DD;
    const float* pBu = pBg + (size_t)FF * DD;

    float4 ra0 = *(const float4*)(pA + ak);
    float4 ra1 = *(const float4*)(pA + ak + 4);
    float4 rg  = *(const float4*)(pBg + bk);
    float4 ru  = *(const float4*)(pBu + bk);

    ull accg2[8][2], accu2[8][2];
    #pragma unroll
    for (int i = 0; i < 8; i++)
        #pragma unroll
        for (int p = 0; p < 2; p++) { accg2[i][p] = 0ull; accu2[i][p] = 0ull; }

    for (int k0 = 0; k0 < DD; k0 += 16) {
        As[ak + 0][am] = ra0.x; As[ak + 1][am] = ra0.y;
        As[ak + 2][am] = ra0.z; As[ak + 3][am] = ra0.w;
        As[ak + 4][am] = ra1.x; As[ak + 5][am] = ra1.y;
        As[ak + 6][am] = ra1.z; As[ak + 7][am] = ra1.w;
        Bg[bk + 0][bnr] = rg.x; Bg[bk + 1][bnr] = rg.y;
        Bg[bk + 2][bnr] = rg.z; Bg[bk + 3][bnr] = rg.w;
        Bu[bk + 0][bnr] = ru.x; Bu[bk + 1][bnr] = ru.y;
        Bu[bk + 2][bnr] = ru.z; Bu[bk + 3][bnr] = ru.w;
        __syncthreads();
        const int k1 = k0 + 16;
        if (k1 < DD) {
            ra0 = *(const float4*)(pA + k1 + ak);
            ra1 = *(const float4*)(pA + k1 + ak + 4);
            rg  = *(const float4*)(pBg + k1 + bk);
            ru  = *(const float4*)(pBu + k1 + bk);
        }
        #pragma unroll
        for (int kk = 0; kk < 16; kk++) {
            float a[8];
            *(float4*)&a[0] = *(const float4*)&As[kk][ty * 8];
            *(float4*)&a[4] = *(const float4*)&As[kk][ty * 8 + 4];
            const ull* bgp = (const ull*)&Bg[kk][tx * 4];
            const ull* bup = (const ull*)&Bu[kk][tx * 4];
            const ull bg0 = bgp[0], bg1 = bgp[1];
            const ull bu0 = bup[0], bu1 = bup[1];
            #pragma unroll
            for (int i = 0; i < 8; i++) {
                const ull a2 = pack2(a[i], a[i]);
                fma2(accg2[i][0], a2, bg0);
                fma2(accg2[i][1], a2, bg1);
                fma2(accu2[i][0], a2, bu0);
                fma2(accu2[i][1], a2, bu1);
            }
        }
        __syncthreads();
    }
    #pragma unroll
    for (int i = 0; i < 8; i++) {
        const int rloc = bm * 128 + ty * 8 + i;
        if (rloc < cnt_e) {
            float* hp = g_H + (size_t)(seg + rloc) * FF + bn * 64 + tx * 4;
            float g0, g1, g2, g3, u0, u1, u2, u3;
            unpack2(accg2[i][0], g0, g1); unpack2(accg2[i][1], g2, g3);
            unpack2(accu2[i][0], u0, u1); unpack2(accu2[i][1], u2, u3);
            float4 hv;
            hv.x = silu_f(g0) * u0;
            hv.y = silu_f(g1) * u1;
            hv.z = silu_f(g2) * u2;
            hv.w = silu_f(g3) * u3;
            *(float4*)hp = hv;
        }
    }
}

// ---------------- fused shared-expert gate+up GEMM (NN, dual acc) ----------
// Block: 128 tokens x 64 hidden. K = DD. B matrices shg/shu are [DD, FSH].
__global__ void __launch_bounds__(256) shared_gateup_kernel(
    const float* __restrict__ x, const float* __restrict__ shg,
    const float* __restrict__ shu)
{
    const int bm = blockIdx.y;
    const int bn = blockIdx.x;          // 64-wide hidden tile

    __shared__ float As[16][128];
    __shared__ float Bg[16][64];
    __shared__ float Bu[16][64];
    const int tid = threadIdx.x;
    const int tx = tid & 15;
    const int ty = tid >> 4;

    const int am = tid >> 1;
    const int ak = (tid & 1) << 3;
    const float* pA = x + (size_t)(bm * 128 + am) * DD;

    const int bkr  = tid >> 4;          // 0..15 (k row)
    const int bc4  = (tid & 15) << 2;   // 0..60 (n col, x4)
    const float* pBg = shg + (size_t)bkr * FSH + bn * 64 + bc4;
    const float* pBu = shu + (size_t)bkr * FSH + bn * 64 + bc4;

    float4 ra0 = *(const float4*)(pA + ak);
    float4 ra1 = *(const float4*)(pA + ak + 4);
    float4 rg  = *(const float4*)(pBg);
    float4 ru  = *(const float4*)(pBu);

    ull accg2[8][2], accu2[8][2];
    #pragma unroll
    for (int i = 0; i < 8; i++)
        #pragma unroll
        for (int p = 0; p < 2; p++) { accg2[i][p] = 0ull; accu2[i][p] = 0ull; }

    for (int k0 = 0; k0 < DD; k0 += 16) {
        As[ak + 0][am] = ra0.x; As[ak + 1][am] = ra0.y;
        As[ak + 2][am] = ra0.z; As[ak + 3][am] = ra0.w;
        As[ak + 4][am] = ra1.x; As[ak + 5][am] = ra1.y;
        As[ak + 6][am] = ra1.z; As[ak + 7][am] = ra1.w;
        *(float4*)&Bg[bkr][bc4] = rg;
        *(float4*)&Bu[bkr][bc4] = ru;
        __syncthreads();
        const int k1 = k0 + 16;
        if (k1 < DD) {
            ra0 = *(const float4*)(pA + k1 + ak);
            ra1 = *(const float4*)(pA + k1 + ak + 4);
            rg  = *(const float4*)(pBg + (size_t)k1 * FSH);
            ru  = *(const float4*)(pBu + (size_t)k1 * FSH);
        }
        #pragma unroll
        for (int kk = 0; kk < 16; kk++) {
            float a[8];
            *(float4*)&a[0] = *(const float4*)&As[kk][ty * 8];
            *(float4*)&a[4] = *(const float4*)&As[kk][ty * 8 + 4];
            const ull* bgp = (const ull*)&Bg[kk][tx * 4];
            const ull* bup = (const ull*)&Bu[kk][tx * 4];
            const ull bg0 = bgp[0], bg1 = bgp[1];
            const ull bu0 = bup[0], bu1 = bup[1];
            #pragma unroll
            for (int i = 0; i < 8; i++) {
                const ull a2 = pack2(a[i], a[i]);
                fma2(accg2[i][0], a2, bg0);
                fma2(accg2[i][1], a2, bg1);
                fma2(accu2[i][0], a2, bu0);
                fma2(accu2[i][1], a2, bu1);
            }
        }
        __syncthreads();
    }
    #pragma unroll
    for (int i = 0; i < 8; i++) {
        float* sp = g_SH + (size_t)(bm * 128 + ty * 8 + i) * FSH + bn * 64 + tx * 4;
        float g0, g1, g2, g3, u0, u1, u2, u3;
        unpack2(accg2[i][0], g0, g1); unpack2(accg2[i][1], g2, g3);
        unpack2(accu2[i][0], u0, u1); unpack2(accu2[i][1], u2, u3);
        float4 sv;
        sv.x = silu_f(g0) * u0;
        sv.y = silu_f(g1) * u1;
        sv.z = silu_f(g2) * u2;
        sv.w = silu_f(g3) * u3;
        *(float4*)sp = sv;
    }
}

// ---------------- shared-expert down GEMM (NN) -> writes out ---------------
// out[t, d] = g_sgate[t] * (g_SH[t, :] @ shd[:, d]).  K = FSH.
__global__ void __launch_bounds__(256) shared_down_kernel(
    const float* __restrict__ shd, float* __restrict__ out)
{
    __shared__ float As[16][128];
    __shared__ float Bs[16][128];
    const int tid = threadIdx.x;
    const int bm = blockIdx.y, bn = blockIdx.x;
    const int tx = tid & 15, ty = tid >> 4;

    const int am = tid >> 1;
    const int ak = (tid & 1) << 3;
    const float* pA = g_SH + (size_t)(bm * 128 + am) * FSH;

    const int bkr = tid >> 5;            // 0..7, rows bkr & bkr+8
    const int bn4 = (tid & 31) << 2;     // 0..124
    const float* pB = shd + bn * 128 + bn4;

    float4 ra0 = *(const float4*)(pA + ak);
    float4 ra1 = *(const float4*)(pA + ak + 4);
    float4 rb0 = *(const float4*)(pB + (size_t)bkr * DD);
    float4 rb1 = *(const float4*)(pB + (size_t)(bkr + 8) * DD);

    ull acc2[8][4];
    #pragma unroll
    for (int i = 0; i < 8; i++)
        #pragma unroll
        for (int p = 0; p < 4; p++) acc2[i][p] = 0ull;

    for (int k0 = 0; k0 < FSH; k0 += 16) {
        As[ak + 0][am] = ra0.x; As[ak + 1][am] = ra0.y;
        As[ak + 2][am] = ra0.z; As[ak + 3][am] = ra0.w;
        As[ak + 4][am] = ra1.x; As[ak + 5][am] = ra1.y;
        As[ak + 6][am] = ra1.z; As[ak + 7][am] = ra1.w;
        *(float4*)&Bs[bkr][bn4]     = rb0;
        *(float4*)&Bs[bkr + 8][bn4] = rb1;
        __syncthreads();
        const int k1 = k0 + 16;
        if (k1 < FSH) {
            ra0 = *(const float4*)(pA + k1 + ak);
            ra1 = *(const float4*)(pA + k1 + ak + 4);
            rb0 = *(const float4*)(pB + (size_t)(k1 + bkr) * DD);
            rb1 = *(const float4*)(pB + (size_t)(k1 + bkr + 8) * DD);
        }
        #pragma unroll
        for (int kk = 0; kk < 16; kk++) {
            float a[8];
            *(float4*)&a[0] = *(const float4*)&As[kk][ty * 8];
            *(float4*)&a[4] = *(const float4*)&As[kk][ty * 8 + 4];
            const ull* bp = (const ull*)&Bs[kk][tx * 8];
            const ull b0 = bp[0], b1 = bp[1], b2 = bp[2], b3 = bp[3];
            #pragma unroll
            for (int i = 0; i < 8; i++) {
                const ull a2 = pack2(a[i], a[i]);
                fma2(acc2[i][0], a2, b0);
                fma2(acc2[i][1], a2, b1);
                fma2(acc2[i][2], a2, b2);
                fma2(acc2[i][3], a2, b3);
            }
        }
        __syncthreads();
    }
    #pragma unroll
    for (int i = 0; i < 8; i++) {
        const int row = bm * 128 + ty * 8 + i;
        const float sg = g_sgate[row];
        float* op = out + (size_t)row * DD + bn * 128 + tx * 8;
        float c0, c1, c2, c3, c4, c5, c6, c7;
        unpack2(acc2[i][0], c0, c1); unpack2(acc2[i][1], c2, c3);
        unpack2(acc2[i][2], c4, c5); unpack2(acc2[i][3], c6, c7);
        *(float4*)(op)     = make_float4(sg * c0, sg * c1, sg * c2, sg * c3);
        *(float4*)(op + 4) = make_float4(sg * c4, sg * c5, sg * c6, sg * c7);
    }
}

// ---------------- MoE down GEMM (NT) -> atomicAdd into out -----------------
// out[tok, d] += wgt * (g_H[slot, :] @ dwn[e, d, :]).  K = FF = 512.
__global__ void __launch_bounds__(256) moe_down_kernel(
    const float* __restrict__ dwn, float* __restrict__ out)
{
    const int e = blockIdx.z;
    const int cnt_e = g_cnt[e];
    const int bm = blockIdx.y;
    if (bm * 128 >= cnt_e) return;
    const int bn = blockIdx.x;
    const int seg = e * CAP;

    __shared__ float As[16][128];
    __shared__ float Bs[16][128];
    const int tid = threadIdx.x;
    const int tx = tid & 15, ty = tid >> 4;

    const int am = tid >> 1;
    const int ak = (tid & 1) << 3;
    const float* pA = g_H + (size_t)(seg + bm * 128 + am) * FF;

    const int bnr = tid >> 1;            // 0..127: one B row (d) per 2 threads
    const float* pB = dwn + ((size_t)e * DD + (size_t)(bn * 128 + bnr)) * FF;

    float4 ra0 = *(const float4*)(pA + ak);
    float4 ra1 = *(const float4*)(pA + ak + 4);
    float4 rb0 = *(const float4*)(pB + ak);
    float4 rb1 = *(const float4*)(pB + ak + 4);

    ull acc2[8][4];
    #pragma unroll
    for (int i = 0; i < 8; i++)
        #pragma unroll
        for (int p = 0; p < 4; p++) acc2[i][p] = 0ull;

    for (int k0 = 0; k0 < FF; k0 += 16) {
        As[ak + 0][am] = ra0.x; As[ak + 1][am] = ra0.y;
        As[ak + 2][am] = ra0.z; As[ak + 3][am] = ra0.w;
        As[ak + 4][am] = ra1.x; As[ak + 5][am] = ra1.y;
        As[ak + 6][am] = ra1.z; As[ak + 7][am] = ra1.w;
        Bs[ak + 0][bnr] = rb0.x; Bs[ak + 1][bnr] = rb0.y;
        Bs[ak + 2][bnr] = rb0.z; Bs[ak + 3][bnr] = rb0.w;
        Bs[ak + 4][bnr] = rb1.x; Bs[ak + 5][bnr] = rb1.y;
        Bs[ak + 6][bnr] = rb1.z; Bs[ak + 7][bnr] = rb1.w;
        __syncthreads();
        const int k1 = k0 + 16;
        if (k1 < FF) {
            ra0 = *(const float4*)(pA + k1 + ak);
            ra1 = *(const float4*)(pA + k1 + ak + 4);
            rb0 = *(const float4*)(pB + k1 + ak);
            rb1 = *(const float4*)(pB + k1 + ak + 4);
        }
        #pragma unroll
        for (int kk = 0; kk < 16; kk++) {
            float a[8];
            *(float4*)&a[0] = *(const float4*)&As[kk][ty * 8];
            *(float4*)&a[4] = *(const float4*)&As[kk][ty * 8 + 4];
            const ull* bp = (const ull*)&Bs[kk][tx * 8];
            const ull b0 = bp[0], b1 = bp[1], b2 = bp[2], b3 = bp[3];
            #pragma unroll
            for (int i = 0; i < 8; i++) {
                const ull a2 = pack2(a[i], a[i]);
                fma2(acc2[i][0], a2, b0);
                fma2(acc2[i][1], a2, b1);
                fma2(acc2[i][2], a2, b2);
                fma2(acc2[i][3], a2, b3);
            }
        }
        __syncthreads();
    }
    #pragma unroll
    for (int i = 0; i < 8; i++) {
        const int rloc = bm * 128 + ty * 8 + i;
        if (rloc < cnt_e) {
            const int   tok = g_tok[seg + rloc];
            const float w   = g_wgt[seg + rloc];
            float* op = out + (size_t)tok * DD + bn * 128 + tx * 8;
            float c0, c1, c2, c3, c4, c5, c6, c7;
            unpack2(acc2[i][0], c0, c1); unpack2(acc2[i][1], c2, c3);
            unpack2(acc2[i][2], c4, c5); unpack2(acc2[i][3], c6, c7);
            atomicAdd(op + 0, w * c0); atomicAdd(op + 1, w * c1);
            atomicAdd(op + 2, w * c2); atomicAdd(op + 3, w * c3);
            atomicAdd(op + 4, w * c4); atomicAdd(op + 5, w * c5);
            atomicAdd(op + 6, w * c6); atomicAdd(op + 7, w * c7);
        }
    }
}

// ------------------------- launch ------------------------------------------
extern "C" void kernel_launch(void* const* d_in, const int* in_sizes, int n_in,
                              void* d_out, int out_size)
{
    const float* x   = (const float*)d_in[0];   // [B,T,D]
    const float* gup = (const float*)d_in[1];   // [E,2F,D]
    const float* dwn = (const float*)d_in[2];   // [E,D,F]
    const float* rw  = (const float*)d_in[3];   // [D,E]
    const float* shg = (const float*)d_in[4];   // [D,FS]
    const float* shu = (const float*)d_in[5];   // [D,FS]
    const float* shd = (const float*)d_in[6];   // [FS,D]
    const float* sgw = (const float*)d_in[7];   // [D,1]
    float* out = (float*)d_out;

    // Router + scatter + aux
    init_kernel<<<1, 32>>>();
    router_kernel<<<NB, 128>>>(x, rw, sgw);
    aux_kernel<<<1, 512>>>(out, out_size);

    // Shared expert: fused gate/up (silu epilogue), then down -> out
    {
        dim3 grid(FSH / 64, NB / 128);          // (32,16)
        shared_gateup_kernel<<<grid, 256>>>(x, shg, shu);
    }
    {
        dim3 grid(DD / 128, NB / 128);          // (8,16)
        shared_down_kernel<<<grid, 256>>>(shd, out);
    }

    // MoE expert path: fused gate/up (silu epilogue), down accumulates to out
    {
        dim3 grid(FF / 64, CAP / 128, EE);      // (8,16,16)
        moe_gateup_kernel<<<grid, 256>>>(x, gup);
    }
    {
        dim3 grid(DD / 128, CAP / 128, EE);     // (8,16,16)
        moe_down_kernel<<<grid, 256>>>(dwn, out);
    }
}